// round 3
// baseline (speedup 1.0000x reference)
#include <cuda_runtime.h>
#include <math.h>

#define BATCH 2
#define CH    64
#define HH    112
#define WW    112
#define HWSZ  (HH*WW)
#define NPIX  (BATCH*HWSZ)
#define RAD   3
#define NN    49

__device__ __align__(256) float g_px  [NPIX*CH];
__device__ __align__(256) float g_sem [NPIX*CH];
__device__ __align__(256) float g_spat[NPIX*CH];
__device__ __align__(256) float g_mid [NPIX*CH];

__device__ __forceinline__ float warp_sum32(float v) {
#pragma unroll
    for (int off = 16; off > 0; off >>= 1)
        v += __shfl_xor_sync(0xffffffffu, v, off);
    return v;
}
__device__ __forceinline__ float grp16_sum(float v) {
#pragma unroll
    for (int off = 8; off > 0; off >>= 1)
        v += __shfl_xor_sync(0xffffffffu, v, off);
    return v;
}

// NCHW -> NHWC transpose of spatial feats into g_spat
__global__ __launch_bounds__(256) void k_transpose(const float* __restrict__ in) {
    __shared__ float t[64 * 33];
    const int blk   = blockIdx.x;
    const int b     = blk / (HWSZ / 32);
    const int pbase = (blk - b * (HWSZ / 32)) * 32;
    const float* inb = in + (size_t)b * CH * HWSZ;
    for (int i = threadIdx.x; i < 2048; i += 256) {
        int c = i >> 5, p = i & 31;
        t[c * 33 + p] = inb[c * HWSZ + pbase + p];
    }
    __syncthreads();
    float* outb = g_spat + ((size_t)b * HWSZ + pbase) * CH;
    for (int i = threadIdx.x; i < 2048; i += 256) {
        int p = i >> 6, c = i & 63;
        outb[p * CH + c] = t[c * 33 + p];
    }
}

// range_proj: conv1x1 -> LN -> SiLU -> conv1x1 ; writes g_px, g_sem (NHWC)
__global__ __launch_bounds__(256) void k_rangeproj(
    const float* __restrict__ sem,
    const float* __restrict__ w1, const float* __restrict__ b1,
    const float* __restrict__ gg, const float* __restrict__ be,
    const float* __restrict__ w2, const float* __restrict__ b2) {
    __shared__ float W1t[64 * 68];
    __shared__ float W2t[64 * 68];
    __shared__ float xsh[16 * 65];
    __shared__ __align__(16) float ysh[16 * 68];
    const int tid = threadIdx.x;
    for (int i = tid; i < 4096; i += 256) {
        int o = i >> 6, c = i & 63;
        W1t[c * 68 + o] = w1[i];
        W2t[c * 68 + o] = w2[i];
    }
    const int oq = tid & 15, pl = tid >> 4;
    const float4 rb1 = *(const float4*)(b1 + oq * 4);
    const float4 rg  = *(const float4*)(gg + oq * 4);
    const float4 rbe = *(const float4*)(be + oq * 4);
    const float4 rb2 = *(const float4*)(b2 + oq * 4);

    for (int grp = blockIdx.x; grp < NPIX / 16; grp += gridDim.x) {
        const int pg0   = grp << 4;
        const int b     = pg0 / HWSZ;
        const int pbase = pg0 - b * HWSZ;
        const float* inb = sem + (size_t)b * CH * HWSZ + pbase;
        __syncthreads();
        for (int i = tid; i < 1024; i += 256) {
            int c = i >> 4, p = i & 15;
            xsh[p * 65 + c] = inb[c * HWSZ + p];
        }
        __syncthreads();
        float* semob = g_sem + (size_t)pg0 * CH;
        for (int i = tid; i < 1024; i += 256) {
            int p = i >> 6, c = i & 63;
            semob[i] = xsh[p * 65 + c];
        }
        float a0 = rb1.x, a1 = rb1.y, a2 = rb1.z, a3 = rb1.w;
        const float* xr = xsh + pl * 65;
#pragma unroll
        for (int c = 0; c < 64; c++) {
            float  xv = xr[c];
            float4 wv = *(const float4*)(W1t + c * 68 + oq * 4);
            a0 = fmaf(wv.x, xv, a0); a1 = fmaf(wv.y, xv, a1);
            a2 = fmaf(wv.z, xv, a2); a3 = fmaf(wv.w, xv, a3);
        }
        float s1 = grp16_sum(a0 + a1 + a2 + a3);
        float s2 = grp16_sum(a0 * a0 + a1 * a1 + a2 * a2 + a3 * a3);
        float u  = s1 * (1.f / 64.f);
        float rs = rsqrtf(fmaxf(s2 * (1.f / 64.f) - u * u, 0.f) + 1e-6f);
        a0 = fmaf(rg.x, (a0 - u) * rs, rbe.x);
        a1 = fmaf(rg.y, (a1 - u) * rs, rbe.y);
        a2 = fmaf(rg.z, (a2 - u) * rs, rbe.z);
        a3 = fmaf(rg.w, (a3 - u) * rs, rbe.w);
        a0 = a0 / (1.f + expf(-a0)); a1 = a1 / (1.f + expf(-a1));
        a2 = a2 / (1.f + expf(-a2)); a3 = a3 / (1.f + expf(-a3));
        *(float4*)(ysh + pl * 68 + oq * 4) = make_float4(a0, a1, a2, a3);
        __syncwarp();
        float z0 = rb2.x, z1 = rb2.y, z2 = rb2.z, z3 = rb2.w;
        const float* yr = ysh + pl * 68;
#pragma unroll
        for (int c = 0; c < 64; c++) {
            float  yv = yr[c];
            float4 wv = *(const float4*)(W2t + c * 68 + oq * 4);
            z0 = fmaf(wv.x, yv, z0); z1 = fmaf(wv.y, yv, z1);
            z2 = fmaf(wv.z, yv, z2); z3 = fmaf(wv.w, yv, z3);
        }
        *(float4*)(g_px + (size_t)(pg0 + pl) * CH + oq * 4) = make_float4(z0, z1, z2, z3);
        __syncwarp();
    }
}

// bilateral weights + fixup gate + neighborhood reduction -> g_mid (NHWC)
__global__ __launch_bounds__(256) void k_bilateral(
    const float* __restrict__ fxw1, const float* __restrict__ fxb1,
    const float* __restrict__ fxg,  const float* __restrict__ fxbe,
    const float* __restrict__ fxw2, const float* __restrict__ fxb2,
    const float* __restrict__ sigp) {
    __shared__ float w1s[49 * 113];
    __shared__ float w2s[49 * 49];
    __shared__ float b1s[49], gs[49], bes[49], b2s[49];
    __shared__ float combw[8][56];
    __shared__ float actw [8][56];
    __shared__ __align__(16) float semw[8][64];

    const int tid = threadIdx.x;
    for (int i = tid; i < 49 * 113; i += 256) w1s[i] = fxw1[i];
    for (int i = tid; i < 49 * 49;  i += 256) w2s[i] = fxw2[i];
    if (tid < 49) { b1s[tid] = fxb1[tid]; gs[tid] = fxg[tid];
                    bes[tid] = fxbe[tid]; b2s[tid] = fxb2[tid]; }
    __syncthreads();

    const int wid = tid >> 5, lane = tid & 31;
    const int half = lane >> 4, q = lane & 15;
    const float sigma   = *sigp;
    const float inv2sig = 0.5f / (sigma * sigma);
    const bool  has2 = (lane < 17);
    const int   o = lane, o2 = lane + 32;
    float* cw  = combw[wid];
    float* aw  = actw[wid];
    float* sw_ = semw[wid];

    for (int grp = blockIdx.x; grp < NPIX / 8; grp += gridDim.x) {
        const int pg = (grp << 3) + wid;
        const int b  = pg / HWSZ;
        const int hw = pg - b * HWSZ;
        const int h  = hw / WW, w = hw - h * WW;
        const size_t bbase = (size_t)b * HWSZ;

        const float4 cv4 = ((const float4*)(g_px + (size_t)pg * CH))[q];
        if (half == 0) {
            float4 sv = ((const float4*)(g_sem + (size_t)pg * CH))[q];
            ((float4*)sw_)[q] = sv;
        }
        __syncwarp();

        for (int k = 0; k < 25; k++) {
            const int n  = (k << 1) + half;
            const int n7 = n / 7;
            const int dy = n7 - RAD, dx = n - n7 * 7 - RAD;
            const int hh = h + dy, ww2 = w + dx;
            const bool val = (n < NN) && ((unsigned)hh < (unsigned)HH) &&
                             ((unsigned)ww2 < (unsigned)WW);
            float d = 0.f;
            if (val) {
                float4 nv = ((const float4*)(g_px + (bbase + hh * WW + ww2) * CH))[q];
                float e0 = nv.x - cv4.x, e1 = nv.y - cv4.y;
                float e2 = nv.z - cv4.z, e3 = nv.w - cv4.w;
                d = fmaf(e0, e0, fmaf(e1, e1, fmaf(e2, e2, e3 * e3)));
            }
            d = grp16_sum(d);
            if (q == 0 && n < NN) {
                float d2s = (float)(dy * dy + dx * dx);
                cw[n] = val ? expf(-fmaf(d, 1.f / 128.f, d2s * inv2sig)) : 0.f;
            }
        }
        __syncwarp();

        float f0 = b1s[o];
        float f1 = has2 ? b1s[o2] : 0.f;
        const float* w1r0 = w1s + o  * 113;
        const float* w1r1 = w1s + o2 * 113;
        for (int n = 0; n < 49; n++) {
            float cn = cw[n];
            f0 = fmaf(w1r0[n], cn, f0);
            if (has2) f1 = fmaf(w1r1[n], cn, f1);
        }
        for (int c = 0; c < 64; c++) {
            float sv = sw_[c];
            f0 = fmaf(w1r0[49 + c], sv, f0);
            if (has2) f1 = fmaf(w1r1[49 + c], sv, f1);
        }
        float s1 = warp_sum32(f0 + (has2 ? f1 : 0.f));
        float s2 = warp_sum32(f0 * f0 + (has2 ? f1 * f1 : 0.f));
        float u  = s1 * (1.f / 49.f);
        float rs = rsqrtf(fmaxf(s2 * (1.f / 49.f) - u * u, 0.f) + 1e-6f);
        float t0 = fmaf(gs[o], (f0 - u) * rs, bes[o]);
        aw[o] = t0 / (1.f + expf(-t0));
        if (has2) {
            float t1 = fmaf(gs[o2], (f1 - u) * rs, bes[o2]);
            aw[o2] = t1 / (1.f + expf(-t1));
        }
        __syncwarp();
        float q0 = b2s[o];
        float q1 = has2 ? b2s[o2] : 0.f;
        const float* w2r0 = w2s + o  * 49;
        const float* w2r1 = w2s + o2 * 49;
        for (int n = 0; n < 49; n++) {
            float an = aw[n];
            q0 = fmaf(w2r0[n], an, q0);
            if (has2) q1 = fmaf(w2r1[n], an, q1);
        }
        cw[o] *= (1.f + 1.f / (1.f + expf(-q0)));
        if (has2) cw[o2] *= (1.f + 1.f / (1.f + expf(-q1)));
        __syncwarp();
        float tot = warp_sum32(cw[lane] + (has2 ? cw[o2] : 0.f));
        const float inv = 1.f / (tot + 1e-7f);

        float a0 = 0.f, a1 = 0.f, a2 = 0.f, a3 = 0.f;
        for (int k = 0; k < 25; k++) {
            const int n  = (k << 1) + half;
            const int n7 = n / 7;
            const int dy = n7 - RAD, dx = n - n7 * 7 - RAD;
            const int hh = h + dy, ww2 = w + dx;
            const bool val = (n < NN) && ((unsigned)hh < (unsigned)HH) &&
                             ((unsigned)ww2 < (unsigned)WW);
            if (val) {
                float cn = cw[n];
                float4 sv = ((const float4*)(g_spat + (bbase + hh * WW + ww2) * CH))[q];
                a0 = fmaf(sv.x, cn, a0); a1 = fmaf(sv.y, cn, a1);
                a2 = fmaf(sv.z, cn, a2); a3 = fmaf(sv.w, cn, a3);
            }
        }
        a0 += __shfl_xor_sync(0xffffffffu, a0, 16);
        a1 += __shfl_xor_sync(0xffffffffu, a1, 16);
        a2 += __shfl_xor_sync(0xffffffffu, a2, 16);
        a3 += __shfl_xor_sync(0xffffffffu, a3, 16);
        if (half == 0)
            ((float4*)(g_mid + (size_t)pg * CH))[q] =
                make_float4(a0 * inv, a1 * inv, a2 * inv, a3 * inv);
        __syncwarp();
    }
}

// output_proj: conv1x1 -> LN -> conv1x1 ; g_mid (NHWC) -> out (NCHW)
__global__ __launch_bounds__(256) void k_outproj(
    const float* __restrict__ w1, const float* __restrict__ b1,
    const float* __restrict__ gg, const float* __restrict__ be,
    const float* __restrict__ w2, const float* __restrict__ b2,
    float* __restrict__ out) {
    __shared__ float W1t[64 * 68];
    __shared__ float W2t[64 * 68];
    __shared__ float xsh[16 * 65];
    __shared__ __align__(16) float ysh[16 * 68];
    __shared__ __align__(16) float zsh[16 * 68];
    const int tid = threadIdx.x;
    for (int i = tid; i < 4096; i += 256) {
        int o = i >> 6, c = i & 63;
        W1t[c * 68 + o] = w1[i];
        W2t[c * 68 + o] = w2[i];
    }
    const int oq = tid & 15, pl = tid >> 4;
    const float4 rb1 = *(const float4*)(b1 + oq * 4);
    const float4 rg  = *(const float4*)(gg + oq * 4);
    const float4 rbe = *(const float4*)(be + oq * 4);
    const float4 rb2 = *(const float4*)(b2 + oq * 4);

    for (int grp = blockIdx.x; grp < NPIX / 16; grp += gridDim.x) {
        const int pg0   = grp << 4;
        const int b     = pg0 / HWSZ;
        const int pbase = pg0 - b * HWSZ;
        const float* inb = g_mid + (size_t)pg0 * CH;
        __syncthreads();
        for (int i = tid; i < 1024; i += 256) {
            int p = i >> 6, c = i & 63;
            xsh[p * 65 + c] = inb[i];
        }
        __syncthreads();
        float a0 = rb1.x, a1 = rb1.y, a2 = rb1.z, a3 = rb1.w;
        const float* xr = xsh + pl * 65;
#pragma unroll
        for (int c = 0; c < 64; c++) {
            float  xv = xr[c];
            float4 wv = *(const float4*)(W1t + c * 68 + oq * 4);
            a0 = fmaf(wv.x, xv, a0); a1 = fmaf(wv.y, xv, a1);
            a2 = fmaf(wv.z, xv, a2); a3 = fmaf(wv.w, xv, a3);
        }
        float s1 = grp16_sum(a0 + a1 + a2 + a3);
        float s2 = grp16_sum(a0 * a0 + a1 * a1 + a2 * a2 + a3 * a3);
        float u  = s1 * (1.f / 64.f);
        float rs = rsqrtf(fmaxf(s2 * (1.f / 64.f) - u * u, 0.f) + 1e-6f);
        a0 = fmaf(rg.x, (a0 - u) * rs, rbe.x);
        a1 = fmaf(rg.y, (a1 - u) * rs, rbe.y);
        a2 = fmaf(rg.z, (a2 - u) * rs, rbe.z);
        a3 = fmaf(rg.w, (a3 - u) * rs, rbe.w);
        *(float4*)(ysh + pl * 68 + oq * 4) = make_float4(a0, a1, a2, a3);
        __syncwarp();
        float z0 = rb2.x, z1 = rb2.y, z2 = rb2.z, z3 = rb2.w;
        const float* yr = ysh + pl * 68;
#pragma unroll
        for (int c = 0; c < 64; c++) {
            float  yv = yr[c];
            float4 wv = *(const float4*)(W2t + c * 68 + oq * 4);
            z0 = fmaf(wv.x, yv, z0); z1 = fmaf(wv.y, yv, z1);
            z2 = fmaf(wv.z, yv, z2); z3 = fmaf(wv.w, yv, z3);
        }
        *(float4*)(zsh + pl * 68 + oq * 4) = make_float4(z0, z1, z2, z3);
        __syncthreads();
        float* outb = out + (size_t)b * CH * HWSZ + pbase;
        for (int i = tid; i < 1024; i += 256) {
            int o = i >> 4, p = i & 15;
            outb[o * HWSZ + p] = zsh[p * 68 + o];
        }
    }
}

extern "C" void kernel_launch(void* const* d_in, const int* in_sizes, int n_in,
                              void* d_out, int out_size) {
    (void)in_sizes; (void)n_in; (void)out_size;
    const float* spatial  = (const float*)d_in[0];
    const float* semantic = (const float*)d_in[1];
    const float* rp_w1 = (const float*)d_in[2];
    const float* rp_b1 = (const float*)d_in[3];
    const float* rp_g  = (const float*)d_in[4];
    const float* rp_be = (const float*)d_in[5];
    const float* rp_w2 = (const float*)d_in[6];
    const float* rp_b2 = (const float*)d_in[7];
    const float* fx_w1 = (const float*)d_in[8];
    const float* fx_b1 = (const float*)d_in[9];
    const float* fx_g  = (const float*)d_in[10];
    const float* fx_be = (const float*)d_in[11];
    const float* fx_w2 = (const float*)d_in[12];
    const float* fx_b2 = (const float*)d_in[13];
    const float* op_w1 = (const float*)d_in[14];
    const float* op_b1 = (const float*)d_in[15];
    const float* op_g  = (const float*)d_in[16];
    const float* op_be = (const float*)d_in[17];
    const float* op_w2 = (const float*)d_in[18];
    const float* op_b2 = (const float*)d_in[19];
    const float* sigma = (const float*)d_in[20];
    float* out = (float*)d_out;

    k_transpose<<<BATCH * (HWSZ / 32), 256>>>(spatial);
    k_rangeproj<<<784, 256>>>(semantic, rp_w1, rp_b1, rp_g, rp_be, rp_w2, rp_b2);
    k_bilateral<<<784, 256>>>(fx_w1, fx_b1, fx_g, fx_be, fx_w2, fx_b2, sigma);
    k_outproj  <<<784, 256>>>(op_w1, op_b1, op_g, op_be, op_w2, op_b2, out);
}

// round 4
// speedup vs baseline: 1.1920x; 1.1920x over previous
#include <cuda_runtime.h>
#include <math.h>

#define BATCH 2
#define CH    64
#define HH    112
#define WW    112
#define HWSZ  (HH*WW)
#define NPIX  (BATCH*HWSZ)
#define RAD   3
#define NN    49

__device__ __align__(256) float g_px  [NPIX*CH];   // range-projected, NHWC
__device__ __align__(256) float g_spat[NPIX*CH];   // spatial feats, NHWC
__device__ __align__(256) float g_mid [NPIX*CH];   // pre-output_proj, NHWC
__device__ __align__(256) float g_fxs [NPIX*CH];   // fixup semantic partial (49 used, 64-padded)

__device__ __forceinline__ float warp_sum32(float v) {
#pragma unroll
    for (int off = 16; off > 0; off >>= 1)
        v += __shfl_xor_sync(0xffffffffu, v, off);
    return v;
}
__device__ __forceinline__ float grp16_sum(float v) {
#pragma unroll
    for (int off = 8; off > 0; off >>= 1)
        v += __shfl_xor_sync(0xffffffffu, v, off);
    return v;
}

// ---------------- NCHW -> NHWC transpose of spatial feats -------------------
__global__ __launch_bounds__(256) void k_transpose(const float* __restrict__ in) {
    __shared__ float t[64 * 33];
    const int blk   = blockIdx.x;
    const int b     = blk / (HWSZ / 32);
    const int pbase = (blk - b * (HWSZ / 32)) * 32;
    const float* inb = in + (size_t)b * CH * HWSZ;
    for (int i = threadIdx.x; i < 2048; i += 256) {
        int c = i >> 5, p = i & 31;
        t[c * 33 + p] = inb[c * HWSZ + pbase + p];
    }
    __syncthreads();
    float* outb = g_spat + ((size_t)b * HWSZ + pbase) * CH;
    for (int i = threadIdx.x; i < 2048; i += 256) {
        int p = i >> 6, c = i & 63;
        outb[p * CH + c] = t[c * 33 + p];
    }
}

// ---------------- range_proj + fixup-semantic GEMM --------------------------
// conv1x1 -> LN -> SiLU -> conv1x1  (writes g_px NHWC)
// plus:  g_fxs[p][o] = sum_c fx_w1[o][49+c] * sem[c][p]   (writes g_fxs)
// 64 pixels per block; each thread: 4 pixels x 4 channels.
__global__ __launch_bounds__(256) void k_rangeproj(
    const float* __restrict__ sem,
    const float* __restrict__ w1, const float* __restrict__ b1,
    const float* __restrict__ gg, const float* __restrict__ be,
    const float* __restrict__ w2, const float* __restrict__ b2,
    const float* __restrict__ fxw1) {
    extern __shared__ float sm[];
    float* W1t = sm;                 // [64][68]  W[c][o]
    float* W2t = W1t + 64 * 68;      // [64][68]
    float* Wf  = W2t + 64 * 68;      // [64][68]  fixup-sem weights (o<49)
    float* xs  = Wf  + 64 * 68;      // [64][64]  x[c][p]
    float* ys  = xs  + 64 * 64;      // [64][68]  y[p][c]
    const int tid = threadIdx.x;
    for (int i = tid; i < 4096; i += 256) {
        int o = i >> 6, c = i & 63;
        W1t[c * 68 + o] = w1[i];
        W2t[c * 68 + o] = w2[i];
        Wf [c * 68 + o] = (o < NN) ? fxw1[o * 113 + 49 + c] : 0.f;
    }
    const int oq = tid & 15, pgrp = tid >> 4, p0 = pgrp << 2;
    const float4 rb1 = *(const float4*)(b1 + oq * 4);
    const float4 rg  = *(const float4*)(gg + oq * 4);
    const float4 rbe = *(const float4*)(be + oq * 4);
    const float4 rb2 = *(const float4*)(b2 + oq * 4);

    const int pg0   = blockIdx.x << 6;
    const int b     = pg0 / HWSZ;
    const int pbase = pg0 - b * HWSZ;
    const float* inb = sem + (size_t)b * CH * HWSZ + pbase;
    for (int i = tid; i < 1024; i += 256) {
        int c = i >> 4, q4 = (i & 15) << 2;
        *(float4*)(xs + c * 64 + q4) = *(const float4*)(inb + c * HWSZ + q4);
    }
    __syncthreads();

    // ---- conv1: A[j] = bias + sum_c W1[c][oq*4..] * x[c][p0+j]
    float4 A0 = rb1, A1 = rb1, A2 = rb1, A3 = rb1;
#pragma unroll 8
    for (int c = 0; c < 64; c++) {
        float4 wv = *(const float4*)(W1t + c * 68 + (oq << 2));
        float4 xv = *(const float4*)(xs  + (c << 6) + p0);
        A0.x = fmaf(wv.x, xv.x, A0.x); A0.y = fmaf(wv.y, xv.x, A0.y);
        A0.z = fmaf(wv.z, xv.x, A0.z); A0.w = fmaf(wv.w, xv.x, A0.w);
        A1.x = fmaf(wv.x, xv.y, A1.x); A1.y = fmaf(wv.y, xv.y, A1.y);
        A1.z = fmaf(wv.z, xv.y, A1.z); A1.w = fmaf(wv.w, xv.y, A1.w);
        A2.x = fmaf(wv.x, xv.z, A2.x); A2.y = fmaf(wv.y, xv.z, A2.y);
        A2.z = fmaf(wv.z, xv.z, A2.z); A2.w = fmaf(wv.w, xv.z, A2.w);
        A3.x = fmaf(wv.x, xv.w, A3.x); A3.y = fmaf(wv.y, xv.w, A3.y);
        A3.z = fmaf(wv.z, xv.w, A3.z); A3.w = fmaf(wv.w, xv.w, A3.w);
    }
    // ---- LN + SiLU per pixel, stage into ys[p][c]
#define LNSILU_STORE(A, J) { \
    float t  = A.x + A.y + A.z + A.w; \
    float t2 = A.x*A.x + A.y*A.y + A.z*A.z + A.w*A.w; \
    float s1 = grp16_sum(t), s2 = grp16_sum(t2); \
    float u  = s1 * (1.f/64.f); \
    float rs = rsqrtf(fmaxf(s2 * (1.f/64.f) - u*u, 0.f) + 1e-6f); \
    A.x = fmaf(rg.x, (A.x-u)*rs, rbe.x); A.y = fmaf(rg.y, (A.y-u)*rs, rbe.y); \
    A.z = fmaf(rg.z, (A.z-u)*rs, rbe.z); A.w = fmaf(rg.w, (A.w-u)*rs, rbe.w); \
    A.x = A.x / (1.f + expf(-A.x)); A.y = A.y / (1.f + expf(-A.y)); \
    A.z = A.z / (1.f + expf(-A.z)); A.w = A.w / (1.f + expf(-A.w)); \
    *(float4*)(ys + (p0 + J) * 68 + (oq << 2)) = A; }
    LNSILU_STORE(A0, 0) LNSILU_STORE(A1, 1) LNSILU_STORE(A2, 2) LNSILU_STORE(A3, 3)
#undef LNSILU_STORE
    __syncwarp();

    // ---- fixup-semantic GEMM (no bias, no LN), reuse accumulators
    A0 = A1 = A2 = A3 = make_float4(0.f, 0.f, 0.f, 0.f);
#pragma unroll 8
    for (int c = 0; c < 64; c++) {
        float4 wv = *(const float4*)(Wf + c * 68 + (oq << 2));
        float4 xv = *(const float4*)(xs + (c << 6) + p0);
        A0.x = fmaf(wv.x, xv.x, A0.x); A0.y = fmaf(wv.y, xv.x, A0.y);
        A0.z = fmaf(wv.z, xv.x, A0.z); A0.w = fmaf(wv.w, xv.x, A0.w);
        A1.x = fmaf(wv.x, xv.y, A1.x); A1.y = fmaf(wv.y, xv.y, A1.y);
        A1.z = fmaf(wv.z, xv.y, A1.z); A1.w = fmaf(wv.w, xv.y, A1.w);
        A2.x = fmaf(wv.x, xv.z, A2.x); A2.y = fmaf(wv.y, xv.z, A2.y);
        A2.z = fmaf(wv.z, xv.z, A2.z); A2.w = fmaf(wv.w, xv.z, A2.w);
        A3.x = fmaf(wv.x, xv.w, A3.x); A3.y = fmaf(wv.y, xv.w, A3.y);
        A3.z = fmaf(wv.z, xv.w, A3.z); A3.w = fmaf(wv.w, xv.w, A3.w);
    }
    {
        float* fo = g_fxs + (size_t)(pg0 + p0) * CH + (oq << 2);
        *(float4*)(fo)          = A0;
        *(float4*)(fo + CH)     = A1;
        *(float4*)(fo + 2 * CH) = A2;
        *(float4*)(fo + 3 * CH) = A3;
    }

    // ---- conv2: Z[j] = b2 + sum_c W2[c][oq*4..] * y[p0+j][c]
    float4 Z0 = rb2, Z1 = rb2, Z2 = rb2, Z3 = rb2;
    const float* yr0 = ys + (p0 + 0) * 68;
    const float* yr1 = ys + (p0 + 1) * 68;
    const float* yr2 = ys + (p0 + 2) * 68;
    const float* yr3 = ys + (p0 + 3) * 68;
#pragma unroll 8
    for (int c = 0; c < 64; c++) {
        float4 wv = *(const float4*)(W2t + c * 68 + (oq << 2));
        float x0 = yr0[c], x1 = yr1[c], x2 = yr2[c], x3 = yr3[c];
        Z0.x = fmaf(wv.x, x0, Z0.x); Z0.y = fmaf(wv.y, x0, Z0.y);
        Z0.z = fmaf(wv.z, x0, Z0.z); Z0.w = fmaf(wv.w, x0, Z0.w);
        Z1.x = fmaf(wv.x, x1, Z1.x); Z1.y = fmaf(wv.y, x1, Z1.y);
        Z1.z = fmaf(wv.z, x1, Z1.z); Z1.w = fmaf(wv.w, x1, Z1.w);
        Z2.x = fmaf(wv.x, x2, Z2.x); Z2.y = fmaf(wv.y, x2, Z2.y);
        Z2.z = fmaf(wv.z, x2, Z2.z); Z2.w = fmaf(wv.w, x2, Z2.w);
        Z3.x = fmaf(wv.x, x3, Z3.x); Z3.y = fmaf(wv.y, x3, Z3.y);
        Z3.z = fmaf(wv.z, x3, Z3.z); Z3.w = fmaf(wv.w, x3, Z3.w);
    }
    {
        float* po = g_px + (size_t)(pg0 + p0) * CH + (oq << 2);
        *(float4*)(po)          = Z0;
        *(float4*)(po + CH)     = Z1;
        *(float4*)(po + 2 * CH) = Z2;
        *(float4*)(po + 3 * CH) = Z3;
    }
}

// ---------------- bilateral weights + fixup gate + reduction ----------------
__global__ __launch_bounds__(256) void k_bilateral(
    const float* __restrict__ fxw1, const float* __restrict__ fxb1,
    const float* __restrict__ fxg,  const float* __restrict__ fxbe,
    const float* __restrict__ fxw2, const float* __restrict__ fxb2,
    const float* __restrict__ sigp) {
    __shared__ float w1s[NN * NN];   // first-49 columns only, stride 49 (odd mod 32)
    __shared__ float w2s[NN * NN];
    __shared__ float b1s[NN], gs[NN], bes[NN], b2s[NN];
    __shared__ float combw[8][56];
    __shared__ float actw [8][56];

    const int tid = threadIdx.x;
    for (int i = tid; i < NN * NN; i += 256) {
        int o = i / NN, n = i - o * NN;
        w1s[i] = fxw1[o * 113 + n];
        w2s[i] = fxw2[i];
    }
    if (tid < NN) { b1s[tid] = fxb1[tid]; gs[tid] = fxg[tid];
                    bes[tid] = fxbe[tid]; b2s[tid] = fxb2[tid]; }
    __syncthreads();

    const int wid = tid >> 5, lane = tid & 31;
    const int half = lane >> 4, q = lane & 15;
    const float sigma   = *sigp;
    const float inv2sig = 0.5f / (sigma * sigma);
    const bool  has2 = (lane < 17);
    const int   o = lane, o2 = lane + 32;
    float* cw = combw[wid];
    float* aw = actw[wid];

    for (int grp = blockIdx.x; grp < NPIX / 8; grp += gridDim.x) {
        const int pg = (grp << 3) + wid;
        const int b  = pg / HWSZ;
        const int hw = pg - b * HWSZ;
        const int h  = hw / WW, w = hw - h * WW;
        const size_t bbase = (size_t)b * HWSZ;

        // prefetch precomputed semantic contribution
        const float* fxrow = g_fxs + (size_t)pg * CH;
        float fb0 = fxrow[o];
        float fb1 = has2 ? fxrow[o2] : 0.f;

        const float4 cv4 = ((const float4*)(g_px + (size_t)pg * CH))[q];

        // pass 1: combined[n] = valid * exp(-(||nbr-ctr||^2/(2C) + d2/(2s^2)))
        for (int k = 0; k < 25; k++) {
            const int n  = (k << 1) + half;
            const int n7 = n / 7;
            const int dy = n7 - RAD, dx = n - n7 * 7 - RAD;
            const int hh = h + dy, ww2 = w + dx;
            const bool val = (n < NN) && ((unsigned)hh < (unsigned)HH) &&
                             ((unsigned)ww2 < (unsigned)WW);
            float d = 0.f;
            if (val) {
                float4 nv = ((const float4*)(g_px + (bbase + hh * WW + ww2) * CH))[q];
                float e0 = nv.x - cv4.x, e1 = nv.y - cv4.y;
                float e2 = nv.z - cv4.z, e3 = nv.w - cv4.w;
                d = fmaf(e0, e0, fmaf(e1, e1, fmaf(e2, e2, e3 * e3)));
            }
            d = grp16_sum(d);
            if (q == 0 && n < NN) {
                float d2s = (float)(dy * dy + dx * dx);
                cw[n] = val ? expf(-fmaf(d, 1.f / 128.f, d2s * inv2sig)) : 0.f;
            }
        }
        __syncwarp();

        // fixup conv1 over combined (semantic part precomputed in fb0/fb1)
        float f0 = b1s[o]  + fb0;
        float f1 = has2 ? (b1s[o2] + fb1) : 0.f;
        const float* w1r0 = w1s + o  * NN;
        const float* w1r1 = w1s + o2 * NN;
        for (int n = 0; n < NN; n++) {
            float cn = cw[n];
            f0 = fmaf(w1r0[n], cn, f0);
            if (has2) f1 = fmaf(w1r1[n], cn, f1);
        }
        float s1 = warp_sum32(f0 + (has2 ? f1 : 0.f));
        float s2 = warp_sum32(f0 * f0 + (has2 ? f1 * f1 : 0.f));
        float u  = s1 * (1.f / 49.f);
        float rs = rsqrtf(fmaxf(s2 * (1.f / 49.f) - u * u, 0.f) + 1e-6f);
        float t0 = fmaf(gs[o], (f0 - u) * rs, bes[o]);
        aw[o] = t0 / (1.f + expf(-t0));
        if (has2) {
            float t1 = fmaf(gs[o2], (f1 - u) * rs, bes[o2]);
            aw[o2] = t1 / (1.f + expf(-t1));
        }
        __syncwarp();
        float q0 = b2s[o];
        float q1 = has2 ? b2s[o2] : 0.f;
        const float* w2r0 = w2s + o  * NN;
        const float* w2r1 = w2s + o2 * NN;
        for (int n = 0; n < NN; n++) {
            float an = aw[n];
            q0 = fmaf(w2r0[n], an, q0);
            if (has2) q1 = fmaf(w2r1[n], an, q1);
        }
        cw[o] *= (1.f + 1.f / (1.f + expf(-q0)));
        if (has2) cw[o2] *= (1.f + 1.f / (1.f + expf(-q1)));
        __syncwarp();
        float tot = warp_sum32(cw[lane] + (has2 ? cw[o2] : 0.f));
        const float inv = 1.f / (tot + 1e-7f);

        // pass 2: weighted reduction of spatial feats
        float a0 = 0.f, a1 = 0.f, a2 = 0.f, a3 = 0.f;
        for (int k = 0; k < 25; k++) {
            const int n  = (k << 1) + half;
            const int n7 = n / 7;
            const int dy = n7 - RAD, dx = n - n7 * 7 - RAD;
            const int hh = h + dy, ww2 = w + dx;
            const bool val = (n < NN) && ((unsigned)hh < (unsigned)HH) &&
                             ((unsigned)ww2 < (unsigned)WW);
            if (val) {
                float cn = cw[n];
                float4 sv = ((const float4*)(g_spat + (bbase + hh * WW + ww2) * CH))[q];
                a0 = fmaf(sv.x, cn, a0); a1 = fmaf(sv.y, cn, a1);
                a2 = fmaf(sv.z, cn, a2); a3 = fmaf(sv.w, cn, a3);
            }
        }
        a0 += __shfl_xor_sync(0xffffffffu, a0, 16);
        a1 += __shfl_xor_sync(0xffffffffu, a1, 16);
        a2 += __shfl_xor_sync(0xffffffffu, a2, 16);
        a3 += __shfl_xor_sync(0xffffffffu, a3, 16);
        if (half == 0)
            ((float4*)(g_mid + (size_t)pg * CH))[q] =
                make_float4(a0 * inv, a1 * inv, a2 * inv, a3 * inv);
        __syncwarp();
    }
}

// ---------------- output_proj: conv1x1 -> LN -> conv1x1 ---------------------
// g_mid (NHWC) -> out (NCHW). 64 pixels per block; 4 px x 4 ch per thread.
__global__ __launch_bounds__(256) void k_outproj(
    const float* __restrict__ w1, const float* __restrict__ b1,
    const float* __restrict__ gg, const float* __restrict__ be,
    const float* __restrict__ w2, const float* __restrict__ b2,
    float* __restrict__ out) {
    extern __shared__ float sm[];
    float* W1t = sm;                // [64][68]
    float* W2t = W1t + 64 * 68;     // [64][68]
    float* xsh = W2t + 64 * 68;     // [64 px][68]  x[p][c]
    float* ysh = xsh + 64 * 68;     // [64 px][68]  y[p][c]
    const int tid = threadIdx.x;
    for (int i = tid; i < 4096; i += 256) {
        int o = i >> 6, c = i & 63;
        W1t[c * 68 + o] = w1[i];
        W2t[c * 68 + o] = w2[i];
    }
    const int oq = tid & 15, pgrp = tid >> 4, p0 = pgrp << 2;
    const float4 rb1 = *(const float4*)(b1 + oq * 4);
    const float4 rg  = *(const float4*)(gg + oq * 4);
    const float4 rbe = *(const float4*)(be + oq * 4);
    const float4 rb2 = *(const float4*)(b2 + oq * 4);

    const int pg0   = blockIdx.x << 6;
    const int b     = pg0 / HWSZ;
    const int pbase = pg0 - b * HWSZ;
    const float* inb = g_mid + (size_t)pg0 * CH;
    for (int i = tid; i < 1024; i += 256) {
        int p = i >> 4, cq = (i & 15) << 2;
        *(float4*)(xsh + p * 68 + cq) = *(const float4*)(inb + p * CH + cq);
    }
    __syncthreads();

    // conv1 (reads x[p][c] scalars broadcast)
    float4 A0 = rb1, A1 = rb1, A2 = rb1, A3 = rb1;
    const float* xr0 = xsh + (p0 + 0) * 68;
    const float* xr1 = xsh + (p0 + 1) * 68;
    const float* xr2 = xsh + (p0 + 2) * 68;
    const float* xr3 = xsh + (p0 + 3) * 68;
#pragma unroll 8
    for (int c = 0; c < 64; c++) {
        float4 wv = *(const float4*)(W1t + c * 68 + (oq << 2));
        float x0 = xr0[c], x1 = xr1[c], x2 = xr2[c], x3 = xr3[c];
        A0.x = fmaf(wv.x, x0, A0.x); A0.y = fmaf(wv.y, x0, A0.y);
        A0.z = fmaf(wv.z, x0, A0.z); A0.w = fmaf(wv.w, x0, A0.w);
        A1.x = fmaf(wv.x, x1, A1.x); A1.y = fmaf(wv.y, x1, A1.y);
        A1.z = fmaf(wv.z, x1, A1.z); A1.w = fmaf(wv.w, x1, A1.w);
        A2.x = fmaf(wv.x, x2, A2.x); A2.y = fmaf(wv.y, x2, A2.y);
        A2.z = fmaf(wv.z, x2, A2.z); A2.w = fmaf(wv.w, x2, A2.w);
        A3.x = fmaf(wv.x, x3, A3.x); A3.y = fmaf(wv.y, x3, A3.y);
        A3.z = fmaf(wv.z, x3, A3.z); A3.w = fmaf(wv.w, x3, A3.w);
    }
    // LN (no SiLU), stage y[p][c]
#define LN_STORE(A, J) { \
    float t  = A.x + A.y + A.z + A.w; \
    float t2 = A.x*A.x + A.y*A.y + A.z*A.z + A.w*A.w; \
    float s1 = grp16_sum(t), s2 = grp16_sum(t2); \
    float u  = s1 * (1.f/64.f); \
    float rs = rsqrtf(fmaxf(s2 * (1.f/64.f) - u*u, 0.f) + 1e-6f); \
    A.x = fmaf(rg.x, (A.x-u)*rs, rbe.x); A.y = fmaf(rg.y, (A.y-u)*rs, rbe.y); \
    A.z = fmaf(rg.z, (A.z-u)*rs, rbe.z); A.w = fmaf(rg.w, (A.w-u)*rs, rbe.w); \
    *(float4*)(ysh + (p0 + J) * 68 + (oq << 2)) = A; }
    LN_STORE(A0, 0) LN_STORE(A1, 1) LN_STORE(A2, 2) LN_STORE(A3, 3)
#undef LN_STORE
    __syncwarp();

    // conv2
    float4 Z0 = rb2, Z1 = rb2, Z2 = rb2, Z3 = rb2;
    const float* yr0 = ysh + (p0 + 0) * 68;
    const float* yr1 = ysh + (p0 + 1) * 68;
    const float* yr2 = ysh + (p0 + 2) * 68;
    const float* yr3 = ysh + (p0 + 3) * 68;
#pragma unroll 8
    for (int c = 0; c < 64; c++) {
        float4 wv = *(const float4*)(W2t + c * 68 + (oq << 2));
        float x0 = yr0[c], x1 = yr1[c], x2 = yr2[c], x3 = yr3[c];
        Z0.x = fmaf(wv.x, x0, Z0.x); Z0.y = fmaf(wv.y, x0, Z0.y);
        Z0.z = fmaf(wv.z, x0, Z0.z); Z0.w = fmaf(wv.w, x0, Z0.w);
        Z1.x = fmaf(wv.x, x1, Z1.x); Z1.y = fmaf(wv.y, x1, Z1.y);
        Z1.z = fmaf(wv.z, x1, Z1.z); Z1.w = fmaf(wv.w, x1, Z1.w);
        Z2.x = fmaf(wv.x, x2, Z2.x); Z2.y = fmaf(wv.y, x2, Z2.y);
        Z2.z = fmaf(wv.z, x2, Z2.z); Z2.w = fmaf(wv.w, x2, Z2.w);
        Z3.x = fmaf(wv.x, x3, Z3.x); Z3.y = fmaf(wv.y, x3, Z3.y);
        Z3.z = fmaf(wv.z, x3, Z3.z); Z3.w = fmaf(wv.w, x3, Z3.w);
    }
    // direct NCHW store: per channel k, a float4 across the 4 pixels
    float* outb = out + (size_t)b * CH * HWSZ + (size_t)(oq * 4) * HWSZ + pbase + p0;
    *(float4*)(outb)            = make_float4(Z0.x, Z1.x, Z2.x, Z3.x);
    *(float4*)(outb + HWSZ)     = make_float4(Z0.y, Z1.y, Z2.y, Z3.y);
    *(float4*)(outb + 2 * HWSZ) = make_float4(Z0.z, Z1.z, Z2.z, Z3.z);
    *(float4*)(outb + 3 * HWSZ) = make_float4(Z0.w, Z1.w, Z2.w, Z3.w);
}

// ---------------- launch ----------------------------------------------------
extern "C" void kernel_launch(void* const* d_in, const int* in_sizes, int n_in,
                              void* d_out, int out_size) {
    (void)in_sizes; (void)n_in; (void)out_size;
    const float* spatial  = (const float*)d_in[0];
    const float* semantic = (const float*)d_in[1];
    const float* rp_w1 = (const float*)d_in[2];
    const float* rp_b1 = (const float*)d_in[3];
    const float* rp_g  = (const float*)d_in[4];
    const float* rp_be = (const float*)d_in[5];
    const float* rp_w2 = (const float*)d_in[6];
    const float* rp_b2 = (const float*)d_in[7];
    const float* fx_w1 = (const float*)d_in[8];
    const float* fx_b1 = (const float*)d_in[9];
    const float* fx_g  = (const float*)d_in[10];
    const float* fx_be = (const float*)d_in[11];
    const float* fx_w2 = (const float*)d_in[12];
    const float* fx_b2 = (const float*)d_in[13];
    const float* op_w1 = (const float*)d_in[14];
    const float* op_b1 = (const float*)d_in[15];
    const float* op_g  = (const float*)d_in[16];
    const float* op_be = (const float*)d_in[17];
    const float* op_w2 = (const float*)d_in[18];
    const float* op_b2 = (const float*)d_in[19];
    const float* sigma = (const float*)d_in[20];
    float* out = (float*)d_out;

    const int SMEM_RP = (3 * 64 * 68 + 64 * 64 + 64 * 68) * 4;  // 86016 B
    const int SMEM_OP = (2 * 64 * 68 + 2 * 64 * 68) * 4;        // 69632 B
    cudaFuncSetAttribute(k_rangeproj, cudaFuncAttributeMaxDynamicSharedMemorySize, SMEM_RP);
    cudaFuncSetAttribute(k_outproj,   cudaFuncAttributeMaxDynamicSharedMemorySize, SMEM_OP);

    k_transpose<<<BATCH * (HWSZ / 32), 256>>>(spatial);
    k_rangeproj<<<NPIX / 64, 256, SMEM_RP>>>(semantic, rp_w1, rp_b1, rp_g, rp_be,
                                             rp_w2, rp_b2, fx_w1);
    k_bilateral<<<784, 256>>>(fx_w1, fx_b1, fx_g, fx_be, fx_w2, fx_b2, sigma);
    k_outproj  <<<NPIX / 64, 256, SMEM_OP>>>(op_w1, op_b1, op_g, op_be,
                                             op_w2, op_b2, out);
}

// round 5
// speedup vs baseline: 1.6868x; 1.4151x over previous
#include <cuda_runtime.h>
#include <math.h>

#define BATCH 2
#define CH    64
#define HH    112
#define WW    112
#define HWSZ  (HH*WW)
#define NPIX  (BATCH*HWSZ)
#define RAD   3
#define NN    49
#define NPAD  52

__device__ __align__(256) float g_px  [NPIX*CH];    // range-projected, NHWC
__device__ __align__(256) float g_spat[NPIX*CH];    // spatial feats, NHWC
__device__ __align__(256) float g_mid [NPIX*CH];    // pre-output_proj, NHWC
__device__ __align__(256) float g_fxs [NPIX*CH];    // fixup semantic partial (64-pad)
__device__ __align__(256) float g_comb[NPIX*NPAD];  // bilateral weights (52-pad)

__device__ __forceinline__ float grp16_sum(float v) {
#pragma unroll
    for (int off = 8; off > 0; off >>= 1)
        v += __shfl_xor_sync(0xffffffffu, v, off);
    return v;
}
__device__ __forceinline__ float sigmf(float x) {
    return 1.f / (1.f + __expf(-x));
}

// ---------------- NCHW -> NHWC transpose of spatial feats -------------------
__global__ __launch_bounds__(256) void k_transpose(const float* __restrict__ in) {
    __shared__ float t[64 * 33];
    const int blk   = blockIdx.x;
    const int b     = blk / (HWSZ / 32);
    const int pbase = (blk - b * (HWSZ / 32)) * 32;
    const float* inb = in + (size_t)b * CH * HWSZ;
    for (int i = threadIdx.x; i < 2048; i += 256) {
        int c = i >> 5, p = i & 31;
        t[c * 33 + p] = inb[c * HWSZ + pbase + p];
    }
    __syncthreads();
    float* outb = g_spat + ((size_t)b * HWSZ + pbase) * CH;
    for (int i = threadIdx.x; i < 2048; i += 256) {
        int p = i >> 6, c = i & 63;
        outb[p * CH + c] = t[c * 33 + p];
    }
}

// ---------------- range_proj + fixup-semantic GEMM --------------------------
__global__ __launch_bounds__(256) void k_rangeproj(
    const float* __restrict__ sem,
    const float* __restrict__ w1, const float* __restrict__ b1,
    const float* __restrict__ gg, const float* __restrict__ be,
    const float* __restrict__ w2, const float* __restrict__ b2,
    const float* __restrict__ fxw1) {
    extern __shared__ float sm[];
    float* W1t = sm;                 // [64][68]
    float* W2t = W1t + 64 * 68;      // [64][68]
    float* Wf  = W2t + 64 * 68;      // [64][68]
    float* xs  = Wf  + 64 * 68;      // [64][64] x[c][p]; later aliased as y[p][c] stride 64
    const int tid = threadIdx.x;
    for (int i = tid; i < 4096; i += 256) {
        int o = i >> 6, c = i & 63;
        W1t[c * 68 + o] = w1[i];
        W2t[c * 68 + o] = w2[i];
        Wf [c * 68 + o] = (o < NN) ? fxw1[o * 113 + 49 + c] : 0.f;
    }
    const int oq = tid & 15, pgrp = tid >> 4, p0 = pgrp << 2;
    const float4 rb1 = *(const float4*)(b1 + oq * 4);
    const float4 rg  = *(const float4*)(gg + oq * 4);
    const float4 rbe = *(const float4*)(be + oq * 4);
    const float4 rb2 = *(const float4*)(b2 + oq * 4);

    const int pg0   = blockIdx.x << 6;
    const int b     = pg0 / HWSZ;
    const int pbase = pg0 - b * HWSZ;
    const float* inb = sem + (size_t)b * CH * HWSZ + pbase;
    for (int i = tid; i < 1024; i += 256) {
        int c = i >> 4, q4 = (i & 15) << 2;
        *(float4*)(xs + c * 64 + q4) = *(const float4*)(inb + c * HWSZ + q4);
    }
    __syncthreads();

    // conv1
    float4 A0 = rb1, A1 = rb1, A2 = rb1, A3 = rb1;
#pragma unroll 8
    for (int c = 0; c < 64; c++) {
        float4 wv = *(const float4*)(W1t + c * 68 + (oq << 2));
        float4 xv = *(const float4*)(xs  + (c << 6) + p0);
        A0.x = fmaf(wv.x, xv.x, A0.x); A0.y = fmaf(wv.y, xv.x, A0.y);
        A0.z = fmaf(wv.z, xv.x, A0.z); A0.w = fmaf(wv.w, xv.x, A0.w);
        A1.x = fmaf(wv.x, xv.y, A1.x); A1.y = fmaf(wv.y, xv.y, A1.y);
        A1.z = fmaf(wv.z, xv.y, A1.z); A1.w = fmaf(wv.w, xv.y, A1.w);
        A2.x = fmaf(wv.x, xv.z, A2.x); A2.y = fmaf(wv.y, xv.z, A2.y);
        A2.z = fmaf(wv.z, xv.z, A2.z); A2.w = fmaf(wv.w, xv.z, A2.w);
        A3.x = fmaf(wv.x, xv.w, A3.x); A3.y = fmaf(wv.y, xv.w, A3.y);
        A3.z = fmaf(wv.z, xv.w, A3.z); A3.w = fmaf(wv.w, xv.w, A3.w);
    }
    // LN + SiLU, keep in registers
    float4 Y0, Y1, Y2, Y3;
#define LNSILU(A, Y) { \
    float t  = A.x + A.y + A.z + A.w; \
    float t2 = A.x*A.x + A.y*A.y + A.z*A.z + A.w*A.w; \
    float s1 = grp16_sum(t), s2 = grp16_sum(t2); \
    float u  = s1 * (1.f/64.f); \
    float rs = rsqrtf(fmaxf(s2 * (1.f/64.f) - u*u, 0.f) + 1e-6f); \
    Y.x = fmaf(rg.x, (A.x-u)*rs, rbe.x); Y.y = fmaf(rg.y, (A.y-u)*rs, rbe.y); \
    Y.z = fmaf(rg.z, (A.z-u)*rs, rbe.z); Y.w = fmaf(rg.w, (A.w-u)*rs, rbe.w); \
    Y.x *= sigmf(Y.x); Y.y *= sigmf(Y.y); Y.z *= sigmf(Y.z); Y.w *= sigmf(Y.w); }
    LNSILU(A0, Y0) LNSILU(A1, Y1) LNSILU(A2, Y2) LNSILU(A3, Y3)
#undef LNSILU

    // fixup-semantic GEMM (reuse accumulators)
    A0 = A1 = A2 = A3 = make_float4(0.f, 0.f, 0.f, 0.f);
#pragma unroll 8
    for (int c = 0; c < 64; c++) {
        float4 wv = *(const float4*)(Wf + c * 68 + (oq << 2));
        float4 xv = *(const float4*)(xs + (c << 6) + p0);
        A0.x = fmaf(wv.x, xv.x, A0.x); A0.y = fmaf(wv.y, xv.x, A0.y);
        A0.z = fmaf(wv.z, xv.x, A0.z); A0.w = fmaf(wv.w, xv.x, A0.w);
        A1.x = fmaf(wv.x, xv.y, A1.x); A1.y = fmaf(wv.y, xv.y, A1.y);
        A1.z = fmaf(wv.z, xv.y, A1.z); A1.w = fmaf(wv.w, xv.y, A1.w);
        A2.x = fmaf(wv.x, xv.z, A2.x); A2.y = fmaf(wv.y, xv.z, A2.y);
        A2.z = fmaf(wv.z, xv.z, A2.z); A2.w = fmaf(wv.w, xv.z, A2.w);
        A3.x = fmaf(wv.x, xv.w, A3.x); A3.y = fmaf(wv.y, xv.w, A3.y);
        A3.z = fmaf(wv.z, xv.w, A3.z); A3.w = fmaf(wv.w, xv.w, A3.w);
    }
    {
        float* fo = g_fxs + (size_t)(pg0 + p0) * CH + (oq << 2);
        *(float4*)(fo)          = A0;
        *(float4*)(fo + CH)     = A1;
        *(float4*)(fo + 2 * CH) = A2;
        *(float4*)(fo + 3 * CH) = A3;
    }
    __syncthreads();              // all xs reads done
    // alias: y[p][c] stride 64 into xs
    *(float4*)(xs + (p0 + 0) * 64 + (oq << 2)) = Y0;
    *(float4*)(xs + (p0 + 1) * 64 + (oq << 2)) = Y1;
    *(float4*)(xs + (p0 + 2) * 64 + (oq << 2)) = Y2;
    *(float4*)(xs + (p0 + 3) * 64 + (oq << 2)) = Y3;
    __syncwarp();

    // conv2
    float4 Z0 = rb2, Z1 = rb2, Z2 = rb2, Z3 = rb2;
    const float* yr0 = xs + (p0 + 0) * 64;
    const float* yr1 = xs + (p0 + 1) * 64;
    const float* yr2 = xs + (p0 + 2) * 64;
    const float* yr3 = xs + (p0 + 3) * 64;
#pragma unroll 8
    for (int c = 0; c < 64; c++) {
        float4 wv = *(const float4*)(W2t + c * 68 + (oq << 2));
        float x0 = yr0[c], x1 = yr1[c], x2 = yr2[c], x3 = yr3[c];
        Z0.x = fmaf(wv.x, x0, Z0.x); Z0.y = fmaf(wv.y, x0, Z0.y);
        Z0.z = fmaf(wv.z, x0, Z0.z); Z0.w = fmaf(wv.w, x0, Z0.w);
        Z1.x = fmaf(wv.x, x1, Z1.x); Z1.y = fmaf(wv.y, x1, Z1.y);
        Z1.z = fmaf(wv.z, x1, Z1.z); Z1.w = fmaf(wv.w, x1, Z1.w);
        Z2.x = fmaf(wv.x, x2, Z2.x); Z2.y = fmaf(wv.y, x2, Z2.y);
        Z2.z = fmaf(wv.z, x2, Z2.z); Z2.w = fmaf(wv.w, x2, Z2.w);
        Z3.x = fmaf(wv.x, x3, Z3.x); Z3.y = fmaf(wv.y, x3, Z3.y);
        Z3.z = fmaf(wv.z, x3, Z3.z); Z3.w = fmaf(wv.w, x3, Z3.w);
    }
    {
        float* po = g_px + (size_t)(pg0 + p0) * CH + (oq << 2);
        *(float4*)(po)          = Z0;
        *(float4*)(po + CH)     = Z1;
        *(float4*)(po + 2 * CH) = Z2;
        *(float4*)(po + 3 * CH) = Z3;
    }
}

// ---------------- k_weights: raw bilateral weights -> g_comb ----------------
__global__ __launch_bounds__(256) void k_weights(const float* __restrict__ sigp) {
    __shared__ float combw[8][56];
    const int tid = threadIdx.x;
    const int wid = tid >> 5, lane = tid & 31;
    const int half = lane >> 4, q = lane & 15;
    const float sigma   = *sigp;
    const float inv2sig = 0.5f / (sigma * sigma);
    float* cw = combw[wid];

    const int pg = (blockIdx.x << 3) + wid;
    const int b  = pg / HWSZ;
    const int hw = pg - b * HWSZ;
    const int h  = hw / WW, w = hw - h * WW;
    const size_t bbase = (size_t)b * HWSZ;

    const float4 cv4 = ((const float4*)(g_px + (size_t)pg * CH))[q];

    for (int k = 0; k < 25; k++) {
        const int n  = (k << 1) + half;
        const int n7 = n / 7;
        const int dy = n7 - RAD, dx = n - n7 * 7 - RAD;
        const int hh = h + dy, ww2 = w + dx;
        const bool val = (n < NN) && ((unsigned)hh < (unsigned)HH) &&
                         ((unsigned)ww2 < (unsigned)WW);
        float d = 0.f;
        if (val) {
            float4 nv = ((const float4*)(g_px + (bbase + hh * WW + ww2) * CH))[q];
            float e0 = nv.x - cv4.x, e1 = nv.y - cv4.y;
            float e2 = nv.z - cv4.z, e3 = nv.w - cv4.w;
            d = fmaf(e0, e0, fmaf(e1, e1, fmaf(e2, e2, e3 * e3)));
        }
        d = grp16_sum(d);
        if (q == 0 && n < NN) {
            float d2s = (float)(dy * dy + dx * dx);
            cw[n] = val ? __expf(-fmaf(d, 1.f / 128.f, d2s * inv2sig)) : 0.f;
        }
    }
    __syncwarp();
    float* co = g_comb + (size_t)pg * NPAD;
    co[lane] = cw[lane];
    if (lane < 20) co[32 + lane] = (lane < 17) ? cw[32 + lane] : 0.f;
}

// ---------------- k_fixup: batched fixup MLP + gate + normalize -------------
// g_comb[p][49] -> conv1(+g_fxs partial) -> LN -> SiLU -> conv2 -> gate -> norm
__global__ __launch_bounds__(256) void k_fixup(
    const float* __restrict__ fxw1, const float* __restrict__ fxb1,
    const float* __restrict__ fxg,  const float* __restrict__ fxbe,
    const float* __restrict__ fxw2, const float* __restrict__ fxb2) {
    extern __shared__ float sm[];
    float* W1t = sm;              // [49][68]  W[n][o], o 64-pad
    float* W2t = W1t + 49 * 68;   // [49][68]
    float* xsh = W2t + 49 * 68;   // [64][52]  combined
    float* ysh = xsh + 64 * NPAD; // [64][52]  activations
    float* sb1 = ysh + 64 * NPAD;
    float* sg  = sb1 + 64;
    float* sbe = sg  + 64;
    float* sb2 = sbe + 64;
    const int tid = threadIdx.x;
    for (int i = tid; i < 49 * 64; i += 256) {
        int n = i >> 6, o = i & 63;
        W1t[n * 68 + o] = (o < NN) ? fxw1[o * 113 + n] : 0.f;
        W2t[n * 68 + o] = (o < NN) ? fxw2[o * NN + n]  : 0.f;
    }
    if (tid < 64) {
        sb1[tid] = (tid < NN) ? fxb1[tid] : 0.f;
        sg [tid] = (tid < NN) ? fxg [tid] : 0.f;
        sbe[tid] = (tid < NN) ? fxbe[tid] : 0.f;
        sb2[tid] = (tid < NN) ? fxb2[tid] : 0.f;
    }
    const int pg0 = blockIdx.x << 6;
    const float* cin = g_comb + (size_t)pg0 * NPAD;
    for (int i = tid; i < 64 * 13; i += 256) {
        int p = i / 13, j4 = (i - p * 13) << 2;
        *(float4*)(xsh + p * NPAD + j4) = *(const float4*)(cin + p * NPAD + j4);
    }
    __syncthreads();

    const int oq = tid & 15, pgrp = tid >> 4, p0 = pgrp << 2;
    const float4 b1v = *(const float4*)(sb1 + (oq << 2));
    const float4 gv  = *(const float4*)(sg  + (oq << 2));
    const float4 bev = *(const float4*)(sbe + (oq << 2));
    const float4 b2v = *(const float4*)(sb2 + (oq << 2));

    // conv1 init = bias + semantic partial
    const float* fxp = g_fxs + (size_t)(pg0 + p0) * CH + (oq << 2);
    float4 F0 = *(const float4*)(fxp);
    float4 F1 = *(const float4*)(fxp + CH);
    float4 F2 = *(const float4*)(fxp + 2 * CH);
    float4 F3 = *(const float4*)(fxp + 3 * CH);
    float4 A0 = make_float4(b1v.x + F0.x, b1v.y + F0.y, b1v.z + F0.z, b1v.w + F0.w);
    float4 A1 = make_float4(b1v.x + F1.x, b1v.y + F1.y, b1v.z + F1.z, b1v.w + F1.w);
    float4 A2 = make_float4(b1v.x + F2.x, b1v.y + F2.y, b1v.z + F2.z, b1v.w + F2.w);
    float4 A3 = make_float4(b1v.x + F3.x, b1v.y + F3.y, b1v.z + F3.z, b1v.w + F3.w);
    const float* xr0 = xsh + (p0 + 0) * NPAD;
    const float* xr1 = xsh + (p0 + 1) * NPAD;
    const float* xr2 = xsh + (p0 + 2) * NPAD;
    const float* xr3 = xsh + (p0 + 3) * NPAD;
#pragma unroll 7
    for (int n = 0; n < NN; n++) {
        float4 wv = *(const float4*)(W1t + n * 68 + (oq << 2));
        float x0 = xr0[n], x1 = xr1[n], x2 = xr2[n], x3 = xr3[n];
        A0.x = fmaf(wv.x, x0, A0.x); A0.y = fmaf(wv.y, x0, A0.y);
        A0.z = fmaf(wv.z, x0, A0.z); A0.w = fmaf(wv.w, x0, A0.w);
        A1.x = fmaf(wv.x, x1, A1.x); A1.y = fmaf(wv.y, x1, A1.y);
        A1.z = fmaf(wv.z, x1, A1.z); A1.w = fmaf(wv.w, x1, A1.w);
        A2.x = fmaf(wv.x, x2, A2.x); A2.y = fmaf(wv.y, x2, A2.y);
        A2.z = fmaf(wv.z, x2, A2.z); A2.w = fmaf(wv.w, x2, A2.w);
        A3.x = fmaf(wv.x, x3, A3.x); A3.y = fmaf(wv.y, x3, A3.y);
        A3.z = fmaf(wv.z, x3, A3.z); A3.w = fmaf(wv.w, x3, A3.w);
    }
    // LN(49) + SiLU, stage into ysh (guarded)
#define LNS(A, J) { \
    float t  = A.x + A.y + A.z + A.w; \
    float t2 = A.x*A.x + A.y*A.y + A.z*A.z + A.w*A.w; \
    float s1 = grp16_sum(t), s2 = grp16_sum(t2); \
    float u  = s1 * (1.f/49.f); \
    float rs = rsqrtf(fmaxf(s2 * (1.f/49.f) - u*u, 0.f) + 1e-6f); \
    A.x = fmaf(gv.x, (A.x-u)*rs, bev.x); A.y = fmaf(gv.y, (A.y-u)*rs, bev.y); \
    A.z = fmaf(gv.z, (A.z-u)*rs, bev.z); A.w = fmaf(gv.w, (A.w-u)*rs, bev.w); \
    A.x *= sigmf(A.x); A.y *= sigmf(A.y); A.z *= sigmf(A.z); A.w *= sigmf(A.w); \
    if (oq < 13) *(float4*)(ysh + (p0 + J) * NPAD + (oq << 2)) = A; }
    LNS(A0, 0) LNS(A1, 1) LNS(A2, 2) LNS(A3, 3)
#undef LNS
    __syncwarp();

    // conv2
    float4 Z0 = b2v, Z1 = b2v, Z2 = b2v, Z3 = b2v;
    const float* yr0 = ysh + (p0 + 0) * NPAD;
    const float* yr1 = ysh + (p0 + 1) * NPAD;
    const float* yr2 = ysh + (p0 + 2) * NPAD;
    const float* yr3 = ysh + (p0 + 3) * NPAD;
#pragma unroll 7
    for (int n = 0; n < NN; n++) {
        float4 wv = *(const float4*)(W2t + n * 68 + (oq << 2));
        float y0 = yr0[n], y1 = yr1[n], y2 = yr2[n], y3 = yr3[n];
        Z0.x = fmaf(wv.x, y0, Z0.x); Z0.y = fmaf(wv.y, y0, Z0.y);
        Z0.z = fmaf(wv.z, y0, Z0.z); Z0.w = fmaf(wv.w, y0, Z0.w);
        Z1.x = fmaf(wv.x, y1, Z1.x); Z1.y = fmaf(wv.y, y1, Z1.y);
        Z1.z = fmaf(wv.z, y1, Z1.z); Z1.w = fmaf(wv.w, y1, Z1.w);
        Z2.x = fmaf(wv.x, y2, Z2.x); Z2.y = fmaf(wv.y, y2, Z2.y);
        Z2.z = fmaf(wv.z, y2, Z2.z); Z2.w = fmaf(wv.w, y2, Z2.w);
        Z3.x = fmaf(wv.x, y3, Z3.x); Z3.y = fmaf(wv.y, y3, Z3.y);
        Z3.z = fmaf(wv.z, y3, Z3.z); Z3.w = fmaf(wv.w, y3, Z3.w);
    }
    // gate + normalize + store
    const float4 zero4 = make_float4(0.f, 0.f, 0.f, 0.f);
    float4 C0 = zero4, C1 = zero4, C2 = zero4, C3 = zero4;
    if (oq < 13) {
        C0 = *(const float4*)(xr0 + (oq << 2));
        C1 = *(const float4*)(xr1 + (oq << 2));
        C2 = *(const float4*)(xr2 + (oq << 2));
        C3 = *(const float4*)(xr3 + (oq << 2));
    }
    C0.x *= 1.f + sigmf(Z0.x); C0.y *= 1.f + sigmf(Z0.y);
    C0.z *= 1.f + sigmf(Z0.z); C0.w *= 1.f + sigmf(Z0.w);
    C1.x *= 1.f + sigmf(Z1.x); C1.y *= 1.f + sigmf(Z1.y);
    C1.z *= 1.f + sigmf(Z1.z); C1.w *= 1.f + sigmf(Z1.w);
    C2.x *= 1.f + sigmf(Z2.x); C2.y *= 1.f + sigmf(Z2.y);
    C2.z *= 1.f + sigmf(Z2.z); C2.w *= 1.f + sigmf(Z2.w);
    C3.x *= 1.f + sigmf(Z3.x); C3.y *= 1.f + sigmf(Z3.y);
    C3.z *= 1.f + sigmf(Z3.z); C3.w *= 1.f + sigmf(Z3.w);
    float i0 = 1.f / (grp16_sum(C0.x + C0.y + C0.z + C0.w) + 1e-7f);
    float i1 = 1.f / (grp16_sum(C1.x + C1.y + C1.z + C1.w) + 1e-7f);
    float i2 = 1.f / (grp16_sum(C2.x + C2.y + C2.z + C2.w) + 1e-7f);
    float i3 = 1.f / (grp16_sum(C3.x + C3.y + C3.z + C3.w) + 1e-7f);
    if (oq < 13) {
        float* co = g_comb + (size_t)(pg0 + p0) * NPAD + (oq << 2);
        *(float4*)(co)            = make_float4(C0.x*i0, C0.y*i0, C0.z*i0, C0.w*i0);
        *(float4*)(co + NPAD)     = make_float4(C1.x*i1, C1.y*i1, C1.z*i1, C1.w*i1);
        *(float4*)(co + 2*NPAD)   = make_float4(C2.x*i2, C2.y*i2, C2.z*i2, C2.w*i2);
        *(float4*)(co + 3*NPAD)   = make_float4(C3.x*i3, C3.y*i3, C3.z*i3, C3.w*i3);
    }
}

// ---------------- k_reduce: weighted neighborhood reduction -----------------
__global__ __launch_bounds__(256) void k_reduce() {
    __shared__ float cws[8][NPAD];
    const int tid = threadIdx.x;
    const int wid = tid >> 5, lane = tid & 31;
    const int half = lane >> 4, q = lane & 15;
    float* cw = cws[wid];

    const int pg = (blockIdx.x << 3) + wid;
    const int b  = pg / HWSZ;
    const int hw = pg - b * HWSZ;
    const int h  = hw / WW, w = hw - h * WW;
    const size_t bbase = (size_t)b * HWSZ;

    if (lane < 13)
        *(float4*)(cw + (lane << 2)) =
            *(const float4*)(g_comb + (size_t)pg * NPAD + (lane << 2));
    __syncwarp();

    float a0 = 0.f, a1 = 0.f, a2 = 0.f, a3 = 0.f;
    for (int k = 0; k < 25; k++) {
        const int n  = (k << 1) + half;
        const int n7 = n / 7;
        const int dy = n7 - RAD, dx = n - n7 * 7 - RAD;
        const int hh = h + dy, ww2 = w + dx;
        const bool val = (n < NN) && ((unsigned)hh < (unsigned)HH) &&
                         ((unsigned)ww2 < (unsigned)WW);
        if (val) {
            float cn = cw[n];
            float4 sv = ((const float4*)(g_spat + (bbase + hh * WW + ww2) * CH))[q];
            a0 = fmaf(sv.x, cn, a0); a1 = fmaf(sv.y, cn, a1);
            a2 = fmaf(sv.z, cn, a2); a3 = fmaf(sv.w, cn, a3);
        }
    }
    a0 += __shfl_xor_sync(0xffffffffu, a0, 16);
    a1 += __shfl_xor_sync(0xffffffffu, a1, 16);
    a2 += __shfl_xor_sync(0xffffffffu, a2, 16);
    a3 += __shfl_xor_sync(0xffffffffu, a3, 16);
    if (half == 0)
        ((float4*)(g_mid + (size_t)pg * CH))[q] = make_float4(a0, a1, a2, a3);
}

// ---------------- output_proj: conv1x1 -> LN -> conv1x1 ---------------------
__global__ __launch_bounds__(256) void k_outproj(
    const float* __restrict__ w1, const float* __restrict__ b1,
    const float* __restrict__ gg, const float* __restrict__ be,
    const float* __restrict__ w2, const float* __restrict__ b2,
    float* __restrict__ out) {
    extern __shared__ float sm[];
    float* W1t = sm;                // [64][68]
    float* W2t = W1t + 64 * 68;     // [64][68]
    float* xsh = W2t + 64 * 68;     // [64][68] x[p][c]; later aliased as y[p][c]
    const int tid = threadIdx.x;
    for (int i = tid; i < 4096; i += 256) {
        int o = i >> 6, c = i & 63;
        W1t[c * 68 + o] = w1[i];
        W2t[c * 68 + o] = w2[i];
    }
    const int oq = tid & 15, pgrp = tid >> 4, p0 = pgrp << 2;
    const float4 rb1 = *(const float4*)(b1 + oq * 4);
    const float4 rg  = *(const float4*)(gg + oq * 4);
    const float4 rbe = *(const float4*)(be + oq * 4);
    const float4 rb2 = *(const float4*)(b2 + oq * 4);

    const int pg0   = blockIdx.x << 6;
    const int b     = pg0 / HWSZ;
    const int pbase = pg0 - b * HWSZ;
    const float* inb = g_mid + (size_t)pg0 * CH;
    for (int i = tid; i < 1024; i += 256) {
        int p = i >> 4, cq = (i & 15) << 2;
        *(float4*)(xsh + p * 68 + cq) = *(const float4*)(inb + p * CH + cq);
    }
    __syncthreads();

    float4 A0 = rb1, A1 = rb1, A2 = rb1, A3 = rb1;
    const float* xr0 = xsh + (p0 + 0) * 68;
    const float* xr1 = xsh + (p0 + 1) * 68;
    const float* xr2 = xsh + (p0 + 2) * 68;
    const float* xr3 = xsh + (p0 + 3) * 68;
#pragma unroll 8
    for (int c = 0; c < 64; c++) {
        float4 wv = *(const float4*)(W1t + c * 68 + (oq << 2));
        float x0 = xr0[c], x1 = xr1[c], x2 = xr2[c], x3 = xr3[c];
        A0.x = fmaf(wv.x, x0, A0.x); A0.y = fmaf(wv.y, x0, A0.y);
        A0.z = fmaf(wv.z, x0, A0.z); A0.w = fmaf(wv.w, x0, A0.w);
        A1.x = fmaf(wv.x, x1, A1.x); A1.y = fmaf(wv.y, x1, A1.y);
        A1.z = fmaf(wv.z, x1, A1.z); A1.w = fmaf(wv.w, x1, A1.w);
        A2.x = fmaf(wv.x, x2, A2.x); A2.y = fmaf(wv.y, x2, A2.y);
        A2.z = fmaf(wv.z, x2, A2.z); A2.w = fmaf(wv.w, x2, A2.w);
        A3.x = fmaf(wv.x, x3, A3.x); A3.y = fmaf(wv.y, x3, A3.y);
        A3.z = fmaf(wv.z, x3, A3.z); A3.w = fmaf(wv.w, x3, A3.w);
    }
    // LN, keep in regs
    float4 Y0, Y1, Y2, Y3;
#define LNO(A, Y) { \
    float t  = A.x + A.y + A.z + A.w; \
    float t2 = A.x*A.x + A.y*A.y + A.z*A.z + A.w*A.w; \
    float s1 = grp16_sum(t), s2 = grp16_sum(t2); \
    float u  = s1 * (1.f/64.f); \
    float rs = rsqrtf(fmaxf(s2 * (1.f/64.f) - u*u, 0.f) + 1e-6f); \
    Y.x = fmaf(rg.x, (A.x-u)*rs, rbe.x); Y.y = fmaf(rg.y, (A.y-u)*rs, rbe.y); \
    Y.z = fmaf(rg.z, (A.z-u)*rs, rbe.z); Y.w = fmaf(rg.w, (A.w-u)*rs, rbe.w); }
    LNO(A0, Y0) LNO(A1, Y1) LNO(A2, Y2) LNO(A3, Y3)
#undef LNO
    __syncwarp();   // all conv1 reads of these rows done (rows private to 16-lane group)
    *(float4*)(xsh + (p0 + 0) * 68 + (oq << 2)) = Y0;
    *(float4*)(xsh + (p0 + 1) * 68 + (oq << 2)) = Y1;
    *(float4*)(xsh + (p0 + 2) * 68 + (oq << 2)) = Y2;
    *(float4*)(xsh + (p0 + 3) * 68 + (oq << 2)) = Y3;
    __syncwarp();

    float4 Z0 = rb2, Z1 = rb2, Z2 = rb2, Z3 = rb2;
#pragma unroll 8
    for (int c = 0; c < 64; c++) {
        float4 wv = *(const float4*)(W2t + c * 68 + (oq << 2));
        float x0 = xr0[c], x1 = xr1[c], x2 = xr2[c], x3 = xr3[c];
        Z0.x = fmaf(wv.x, x0, Z0.x); Z0.y = fmaf(wv.y, x0, Z0.y);
        Z0.z = fmaf(wv.z, x0, Z0.z); Z0.w = fmaf(wv.w, x0, Z0.w);
        Z1.x = fmaf(wv.x, x1, Z1.x); Z1.y = fmaf(wv.y, x1, Z1.y);
        Z1.z = fmaf(wv.z, x1, Z1.z); Z1.w = fmaf(wv.w, x1, Z1.w);
        Z2.x = fmaf(wv.x, x2, Z2.x); Z2.y = fmaf(wv.y, x2, Z2.y);
        Z2.z = fmaf(wv.z, x2, Z2.z); Z2.w = fmaf(wv.w, x2, Z2.w);
        Z3.x = fmaf(wv.x, x3, Z3.x); Z3.y = fmaf(wv.y, x3, Z3.y);
        Z3.z = fmaf(wv.z, x3, Z3.z); Z3.w = fmaf(wv.w, x3, Z3.w);
    }
    float* outb = out + (size_t)b * CH * HWSZ + (size_t)(oq * 4) * HWSZ + pbase + p0;
    *(float4*)(outb)            = make_float4(Z0.x, Z1.x, Z2.x, Z3.x);
    *(float4*)(outb + HWSZ)     = make_float4(Z0.y, Z1.y, Z2.y, Z3.y);
    *(float4*)(outb + 2 * HWSZ) = make_float4(Z0.z, Z1.z, Z2.z, Z3.z);
    *(float4*)(outb + 3 * HWSZ) = make_float4(Z0.w, Z1.w, Z2.w, Z3.w);
}

// ---------------- launch ----------------------------------------------------
extern "C" void kernel_launch(void* const* d_in, const int* in_sizes, int n_in,
                              void* d_out, int out_size) {
    (void)in_sizes; (void)n_in; (void)out_size;
    const float* spatial  = (const float*)d_in[0];
    const float* semantic = (const float*)d_in[1];
    const float* rp_w1 = (const float*)d_in[2];
    const float* rp_b1 = (const float*)d_in[3];
    const float* rp_g  = (const float*)d_in[4];
    const float* rp_be = (const float*)d_in[5];
    const float* rp_w2 = (const float*)d_in[6];
    const float* rp_b2 = (const float*)d_in[7];
    const float* fx_w1 = (const float*)d_in[8];
    const float* fx_b1 = (const float*)d_in[9];
    const float* fx_g  = (const float*)d_in[10];
    const float* fx_be = (const float*)d_in[11];
    const float* fx_w2 = (const float*)d_in[12];
    const float* fx_b2 = (const float*)d_in[13];
    const float* op_w1 = (const float*)d_in[14];
    const float* op_b1 = (const float*)d_in[15];
    const float* op_g  = (const float*)d_in[16];
    const float* op_be = (const float*)d_in[17];
    const float* op_w2 = (const float*)d_in[18];
    const float* op_b2 = (const float*)d_in[19];
    const float* sigma = (const float*)d_in[20];
    float* out = (float*)d_out;

    const int SMEM_RP = (3 * 64 * 68 + 64 * 64) * 4;                  // 68608 B
    const int SMEM_OP = (3 * 64 * 68) * 4;                            // 52224 B
    const int SMEM_FX = (2 * 49 * 68 + 2 * 64 * NPAD + 4 * 64) * 4;   // 54304 B
    cudaFuncSetAttribute(k_rangeproj, cudaFuncAttributeMaxDynamicSharedMemorySize, SMEM_RP);
    cudaFuncSetAttribute(k_outproj,   cudaFuncAttributeMaxDynamicSharedMemorySize, SMEM_OP);
    cudaFuncSetAttribute(k_fixup,     cudaFuncAttributeMaxDynamicSharedMemorySize, SMEM_FX);

    k_transpose<<<BATCH * (HWSZ / 32), 256>>>(spatial);
    k_rangeproj<<<NPIX / 64, 256, SMEM_RP>>>(semantic, rp_w1, rp_b1, rp_g, rp_be,
                                             rp_w2, rp_b2, fx_w1);
    k_weights<<<NPIX / 8, 256>>>(sigma);
    k_fixup<<<NPIX / 64, 256, SMEM_FX>>>(fx_w1, fx_b1, fx_g, fx_be, fx_w2, fx_b2);
    k_reduce<<<NPIX / 8, 256>>>();
    k_outproj<<<NPIX / 64, 256, SMEM_OP>>>(op_w1, op_b1, op_g, op_be,
                                           op_w2, op_b2, out);
}